// round 1
// baseline (speedup 1.0000x reference)
#include <cuda_runtime.h>
#include <math.h>

#define N_NODES 50000
#define N_EDGES 800000
#define IN_F 128
#define OUT_F 128
#define HEADS 8
#define HEAD_DIM 16
#define EDGE_F 64

// ---------------- scratch (static device globals; no allocation) ----------------
__device__ float g_q[(size_t)N_NODES * OUT_F];
__device__ float g_k[(size_t)N_NODES * OUT_F];
__device__ float g_v[(size_t)N_NODES * OUT_F];
__device__ float g_scores[(size_t)N_EDGES * HEADS];
__device__ float g_agg[(size_t)N_NODES * OUT_F];
__device__ int   g_deg[N_NODES];
__device__ int   g_off[N_NODES + 1];
__device__ int   g_cursor[N_NODES];
__device__ int   g_elist[N_EDGES];
__device__ int   g_bsum[64];

#define SCAN_NB 49   // ceil(50000/1024)

// ---------------- QKV projection: out = x @ W + b for 3 matrices ----------------
// Block: 384 threads, tile = 64 nodes. m = tid/128 selects matrix.
// Per thread: 4 output cols x 16 nodes (float4 acc[16]) -> 16 FFMA per LDS.128.
__global__ void __launch_bounds__(384) k_qkv(
    const float* __restrict__ x,
    const float* __restrict__ Wq, const float* __restrict__ bq,
    const float* __restrict__ Wk, const float* __restrict__ bk,
    const float* __restrict__ Wv, const float* __restrict__ bv)
{
    __shared__ float xs[128 * 64];   // xs[i*64 + n], 32 KB
    const int n0 = blockIdx.x * 64;
    const int nvalid = min(64, N_NODES - n0);
    const int tid = threadIdx.x;

    // load tile transposed: lane varies n (conflict-free STS), loop varies i4
    for (int j = tid; j < 2048; j += 384) {
        int n = j & 63;
        int i4 = j >> 6;               // 0..31 (float4 index along feature dim)
        if (n < nvalid) {
            float4 val = reinterpret_cast<const float4*>(x)[(size_t)(n0 + n) * 32 + i4];
            xs[(i4 * 4 + 0) * 64 + n] = val.x;
            xs[(i4 * 4 + 1) * 64 + n] = val.y;
            xs[(i4 * 4 + 2) * 64 + n] = val.z;
            xs[(i4 * 4 + 3) * 64 + n] = val.w;
        } else {
            xs[(i4 * 4 + 0) * 64 + n] = 0.f;
            xs[(i4 * 4 + 1) * 64 + n] = 0.f;
            xs[(i4 * 4 + 2) * 64 + n] = 0.f;
            xs[(i4 * 4 + 3) * 64 + n] = 0.f;
        }
    }
    __syncthreads();

    const int m  = tid >> 7;            // 0=Q, 1=K, 2=V (warp-uniform)
    const int tt = tid & 127;
    const int c4 = (tt & 31) * 4;       // output col base
    const int nb = (tt >> 5) * 16;      // node base within tile

    const float* W    = (m == 0) ? Wq : (m == 1) ? Wk : Wv;
    const float* bias = (m == 0) ? bq : (m == 1) ? bk : bv;
    float* outp       = (m == 0) ? g_q : (m == 1) ? g_k : g_v;

    float4 acc[16];
#pragma unroll
    for (int n = 0; n < 16; n++) acc[n] = make_float4(0.f, 0.f, 0.f, 0.f);

#pragma unroll 4
    for (int i = 0; i < 128; i++) {
        float4 w4 = reinterpret_cast<const float4*>(W)[i * 32 + (c4 >> 2)];
        const float* xr = &xs[i * 64 + nb];
#pragma unroll
        for (int nn = 0; nn < 16; nn += 4) {
            float4 xv = *reinterpret_cast<const float4*>(&xr[nn]);
            acc[nn + 0].x += xv.x * w4.x; acc[nn + 0].y += xv.x * w4.y;
            acc[nn + 0].z += xv.x * w4.z; acc[nn + 0].w += xv.x * w4.w;
            acc[nn + 1].x += xv.y * w4.x; acc[nn + 1].y += xv.y * w4.y;
            acc[nn + 1].z += xv.y * w4.z; acc[nn + 1].w += xv.y * w4.w;
            acc[nn + 2].x += xv.z * w4.x; acc[nn + 2].y += xv.z * w4.y;
            acc[nn + 2].z += xv.z * w4.z; acc[nn + 2].w += xv.z * w4.w;
            acc[nn + 3].x += xv.w * w4.x; acc[nn + 3].y += xv.w * w4.y;
            acc[nn + 3].z += xv.w * w4.z; acc[nn + 3].w += xv.w * w4.w;
        }
    }

    float4 b4 = reinterpret_cast<const float4*>(bias)[c4 >> 2];
#pragma unroll
    for (int n = 0; n < 16; n++) {
        int node = n0 + nb + n;
        if (node < N_NODES) {
            float4 r = make_float4(acc[n].x + b4.x, acc[n].y + b4.y,
                                   acc[n].z + b4.z, acc[n].w + b4.w);
            reinterpret_cast<float4*>(outp)[(size_t)node * 32 + (c4 >> 2)] = r;
        }
    }
}

// ---------------- degree count ----------------
__global__ void k_count(const int* __restrict__ ei)
{
    int e = blockIdx.x * blockDim.x + threadIdx.x;
    if (e < N_EDGES) {
        int t = ei[N_EDGES + e];
        atomicAdd(&g_deg[t], 1);
    }
}

// ---------------- 3-phase exclusive scan over g_deg -> g_off ----------------
__global__ void k_scanA()
{
    __shared__ int wsum[32];
    int b = blockIdx.x, tid = threadIdx.x;
    int i = b * 1024 + tid;
    int val = (i < N_NODES) ? g_deg[i] : 0;
    int lane = tid & 31, w = tid >> 5;
    for (int d = 16; d > 0; d >>= 1) val += __shfl_xor_sync(0xffffffffu, val, d);
    if (lane == 0) wsum[w] = val;
    __syncthreads();
    if (w == 0) {
        int s = wsum[lane];
        for (int d = 16; d > 0; d >>= 1) s += __shfl_xor_sync(0xffffffffu, s, d);
        if (lane == 0) g_bsum[b] = s;
    }
}

__global__ void k_scanB()
{
    if (threadIdx.x == 0) {
        int run = 0;
        for (int b = 0; b < SCAN_NB; b++) {
            int t = g_bsum[b];
            g_bsum[b] = run;
            run += t;
        }
    }
}

__global__ void k_scanC()
{
    __shared__ int wsum[32];
    int b = blockIdx.x, tid = threadIdx.x;
    int i = b * 1024 + tid;
    int val = (i < N_NODES) ? g_deg[i] : 0;
    int lane = tid & 31, w = tid >> 5;
    int incl = val;
    for (int d = 1; d < 32; d <<= 1) {
        int t = __shfl_up_sync(0xffffffffu, incl, d);
        if (lane >= d) incl += t;
    }
    if (lane == 31) wsum[w] = incl;
    __syncthreads();
    if (w == 0) {
        int s = wsum[lane];
        for (int d = 1; d < 32; d <<= 1) {
            int t = __shfl_up_sync(0xffffffffu, s, d);
            if (lane >= d) s += t;
        }
        wsum[lane] = s;   // inclusive warp totals
    }
    __syncthreads();
    int warp_off = (w == 0) ? 0 : wsum[w - 1];
    int excl = incl - val + warp_off + g_bsum[b];
    if (i < N_NODES) {
        g_off[i] = excl;
        if (i == N_NODES - 1) g_off[N_NODES] = excl + val;
    }
}

// ---------------- fill CSR edge list ----------------
__global__ void k_fill(const int* __restrict__ ei)
{
    int e = blockIdx.x * blockDim.x + threadIdx.x;
    if (e < N_EDGES) {
        int t = ei[N_EDGES + e];
        int pos = atomicAdd(&g_cursor[t], 1);
        g_elist[pos] = e;
    }
}

// ---------------- per-edge scores: q[t].k[s] per head * scale + ef@We + be ----
// 1 warp per edge. lane = h*4 + j; lane owns dims 4*lane..4*lane+3.
__global__ void __launch_bounds__(256) k_scores(
    const int* __restrict__ ei, const float* __restrict__ ef,
    const float* __restrict__ We, const float* __restrict__ be)
{
    int e = blockIdx.x * 8 + (threadIdx.x >> 5);
    if (e >= N_EDGES) return;
    int lane = threadIdx.x & 31;
    int h = lane >> 2, j = lane & 3;

    // per-lane slice of We: f in [16j, 16j+16), head h  (2KB matrix, L1-resident)
    float wreg[16];
#pragma unroll
    for (int ff = 0; ff < 16; ff++) wreg[ff] = We[(j * 16 + ff) * 8 + h];

    int s = ei[e];
    int t = ei[N_EDGES + e];

    float4 q4 = reinterpret_cast<const float4*>(g_q)[(size_t)t * 32 + lane];
    float4 k4 = reinterpret_cast<const float4*>(g_k)[(size_t)s * 32 + lane];
    float dp = q4.x * k4.x + q4.y * k4.y + q4.z * k4.z + q4.w * k4.w;

    float bias = 0.f;
    const float4* ef4 = reinterpret_cast<const float4*>(ef) + (size_t)e * 16;
#pragma unroll
    for (int f4 = 0; f4 < 4; f4++) {
        float4 v = ef4[j * 4 + f4];
        bias += v.x * wreg[f4 * 4 + 0] + v.y * wreg[f4 * 4 + 1]
              + v.z * wreg[f4 * 4 + 2] + v.w * wreg[f4 * 4 + 3];
    }

    dp   += __shfl_xor_sync(0xffffffffu, dp,   1);
    dp   += __shfl_xor_sync(0xffffffffu, dp,   2);
    bias += __shfl_xor_sync(0xffffffffu, bias, 1);
    bias += __shfl_xor_sync(0xffffffffu, bias, 2);

    if (j == 0) g_scores[(size_t)e * 8 + h] = dp * 0.25f + bias + be[h];
}

// ---------------- segment softmax + weighted V aggregation (warp per node) ----
__global__ void __launch_bounds__(256) k_agg(const int* __restrict__ ei)
{
    int node = (blockIdx.x * blockDim.x + threadIdx.x) >> 5;
    if (node >= N_NODES) return;
    int lane = threadIdx.x & 31;
    int start = g_off[node], end = g_off[node + 1];

    // pass 1: per-head max (4 edges in parallel: sub = lane/8, head = lane%8)
    int h8 = lane & 7, sub = lane >> 3;
    float m = -INFINITY;
    for (int b = start; b < end; b += 4) {
        int idx = b + sub;
        if (idx < end) {
            int e = g_elist[idx];
            m = fmaxf(m, g_scores[(size_t)e * 8 + h8]);
        }
    }
    m = fmaxf(m, __shfl_xor_sync(0xffffffffu, m, 8));
    m = fmaxf(m, __shfl_xor_sync(0xffffffffu, m, 16));
    // broadcast: max for head (lane>>2) lives on lane (lane>>2) among 0..7
    float mh = __shfl_sync(0xffffffffu, m, lane >> 2);

    // pass 2: accumulate exp * v and denominator
    int h = lane >> 2;
    float4 acc = make_float4(0.f, 0.f, 0.f, 0.f);
    float den = 0.f;
    for (int idx = start; idx < end; idx++) {
        int e = g_elist[idx];
        int s = ei[e];
        float p = __expf(g_scores[(size_t)e * 8 + h] - mh);
        float4 v4 = reinterpret_cast<const float4*>(g_v)[(size_t)s * 32 + lane];
        acc.x += p * v4.x; acc.y += p * v4.y;
        acc.z += p * v4.z; acc.w += p * v4.w;
        den += p;
    }
    float inv = 1.f / (den + 1e-10f);
    float4 r = make_float4(acc.x * inv, acc.y * inv, acc.z * inv, acc.w * inv);
    reinterpret_cast<float4*>(g_agg)[(size_t)node * 32 + lane] = r;
}

// ---------------- output GEMM: out = agg @ Wo + bo ----------------
__global__ void __launch_bounds__(128) k_out(
    const float* __restrict__ Wo, const float* __restrict__ bo,
    float* __restrict__ out)
{
    __shared__ float xs[128 * 64];
    const int n0 = blockIdx.x * 64;
    const int nvalid = min(64, N_NODES - n0);
    const int tid = threadIdx.x;

    for (int j = tid; j < 2048; j += 128) {
        int n = j & 63;
        int i4 = j >> 6;
        if (n < nvalid) {
            float4 val = reinterpret_cast<const float4*>(g_agg)[(size_t)(n0 + n) * 32 + i4];
            xs[(i4 * 4 + 0) * 64 + n] = val.x;
            xs[(i4 * 4 + 1) * 64 + n] = val.y;
            xs[(i4 * 4 + 2) * 64 + n] = val.z;
            xs[(i4 * 4 + 3) * 64 + n] = val.w;
        } else {
            xs[(i4 * 4 + 0) * 64 + n] = 0.f;
            xs[(i4 * 4 + 1) * 64 + n] = 0.f;
            xs[(i4 * 4 + 2) * 64 + n] = 0.f;
            xs[(i4 * 4 + 3) * 64 + n] = 0.f;
        }
    }
    __syncthreads();

    const int c4 = (tid & 31) * 4;
    const int nb = (tid >> 5) * 16;

    float4 acc[16];
#pragma unroll
    for (int n = 0; n < 16; n++) acc[n] = make_float4(0.f, 0.f, 0.f, 0.f);

#pragma unroll 4
    for (int i = 0; i < 128; i++) {
        float4 w4 = reinterpret_cast<const float4*>(Wo)[i * 32 + (c4 >> 2)];
        const float* xr = &xs[i * 64 + nb];
#pragma unroll
        for (int nn = 0; nn < 16; nn += 4) {
            float4 xv = *reinterpret_cast<const float4*>(&xr[nn]);
            acc[nn + 0].x += xv.x * w4.x; acc[nn + 0].y += xv.x * w4.y;
            acc[nn + 0].z += xv.x * w4.z; acc[nn + 0].w += xv.x * w4.w;
            acc[nn + 1].x += xv.y * w4.x; acc[nn + 1].y += xv.y * w4.y;
            acc[nn + 1].z += xv.y * w4.z; acc[nn + 1].w += xv.y * w4.w;
            acc[nn + 2].x += xv.z * w4.x; acc[nn + 2].y += xv.z * w4.y;
            acc[nn + 2].z += xv.z * w4.z; acc[nn + 2].w += xv.z * w4.w;
            acc[nn + 3].x += xv.w * w4.x; acc[nn + 3].y += xv.w * w4.y;
            acc[nn + 3].z += xv.w * w4.z; acc[nn + 3].w += xv.w * w4.w;
        }
    }

    float4 b4 = reinterpret_cast<const float4*>(bo)[c4 >> 2];
#pragma unroll
    for (int n = 0; n < 16; n++) {
        int node = n0 + nb + n;
        if (node < N_NODES) {
            float4 r = make_float4(acc[n].x + b4.x, acc[n].y + b4.y,
                                   acc[n].z + b4.z, acc[n].w + b4.w);
            reinterpret_cast<float4*>(out)[(size_t)node * 32 + (c4 >> 2)] = r;
        }
    }
}

// ---------------- launch ----------------
extern "C" void kernel_launch(void* const* d_in, const int* in_sizes, int n_in,
                              void* d_out, int out_size)
{
    const float* x  = (const float*)d_in[0];
    const int*   ei = (const int*)  d_in[1];
    const float* ef = (const float*)d_in[2];
    const float* Wq = (const float*)d_in[3];
    const float* bq = (const float*)d_in[4];
    const float* Wk = (const float*)d_in[5];
    const float* bk = (const float*)d_in[6];
    const float* Wv = (const float*)d_in[7];
    const float* bv = (const float*)d_in[8];
    const float* We = (const float*)d_in[9];
    const float* be = (const float*)d_in[10];
    const float* Wo = (const float*)d_in[11];
    const float* bo = (const float*)d_in[12];
    float* out = (float*)d_out;

    void* degPtr = nullptr; void* offPtr = nullptr; void* curPtr = nullptr;
    cudaGetSymbolAddress(&degPtr, g_deg);
    cudaGetSymbolAddress(&offPtr, g_off);
    cudaGetSymbolAddress(&curPtr, g_cursor);

    cudaMemsetAsync(degPtr, 0, N_NODES * sizeof(int), 0);

    k_qkv<<<(N_NODES + 63) / 64, 384>>>(x, Wq, bq, Wk, bk, Wv, bv);
    k_count<<<(N_EDGES + 255) / 256, 256>>>(ei);
    k_scanA<<<SCAN_NB, 1024>>>();
    k_scanB<<<1, 32>>>();
    k_scanC<<<SCAN_NB, 1024>>>();
    cudaMemcpyAsync(curPtr, offPtr, N_NODES * sizeof(int),
                    cudaMemcpyDeviceToDevice, 0);
    k_fill<<<(N_EDGES + 255) / 256, 256>>>(ei);
    k_scores<<<(N_EDGES + 7) / 8, 256>>>(ei, ef, We, be);
    k_agg<<<(N_NODES * 32 + 255) / 256, 256>>>(ei);
    k_out<<<(N_NODES + 63) / 64, 128>>>(Wo, bo, out);
}

// round 2
// speedup vs baseline: 1.0606x; 1.0606x over previous
#include <cuda_runtime.h>
#include <math.h>

#define N_NODES 50000
#define N_EDGES 800000
#define IN_F 128
#define OUT_F 128
#define HEADS 8
#define HEAD_DIM 16
#define EDGE_F 64

typedef unsigned long long u64;

// ---------------- scratch (static device globals; no allocation) ----------------
__device__ float g_q[(size_t)N_NODES * OUT_F];
__device__ float g_k[(size_t)N_NODES * OUT_F];
__device__ float g_v[(size_t)N_NODES * OUT_F];
__device__ float g_scores[(size_t)N_EDGES * HEADS];   // CSR-ordered by target
__device__ float g_agg[(size_t)N_NODES * OUT_F];
__device__ int   g_deg[N_NODES];
__device__ int   g_off[N_NODES + 1];
__device__ int   g_cursor[N_NODES];
__device__ int   g_src[N_EDGES];                       // CSR-ordered source node
__device__ int   g_epos[N_EDGES];                      // edge -> CSR slot
__device__ int   g_bsum[64];

#define SCAN_NB 49   // ceil(50000/1024)

// ---------------- packed fp32x2 helpers (Blackwell FFMA2 path) ----------------
__device__ __forceinline__ u64 pack2(float a, float b) {
    u64 r; asm("mov.b64 %0, {%1, %2};" : "=l"(r) : "f"(a), "f"(b)); return r;
}
__device__ __forceinline__ float2 unpack2(u64 v) {
    float2 r; asm("mov.b64 {%0, %1}, %2;" : "=f"(r.x), "=f"(r.y) : "l"(v)); return r;
}
__device__ __forceinline__ void ffma2(u64& d, u64 a, u64 b) {
    asm("fma.rn.f32x2 %0, %1, %2, %0;" : "+l"(d) : "l"(a), "l"(b));
}

// ---------------- QKV projection: out = x @ W + b for 3 matrices ----------------
// Block: 384 threads, tile = 64 nodes. m = tid/128 selects matrix.
// Node dim packed in f32x2 pairs: 32 FFMA2 per i per thread (2x fma-pipe rate).
__global__ void __launch_bounds__(384) k_qkv(
    const float* __restrict__ x,
    const float* __restrict__ Wq, const float* __restrict__ bq,
    const float* __restrict__ Wk, const float* __restrict__ bk,
    const float* __restrict__ Wv, const float* __restrict__ bv)
{
    __shared__ float xs[128 * 64];   // xs[i*64 + n], 32 KB
    const int n0 = blockIdx.x * 64;
    const int nvalid = min(64, N_NODES - n0);
    const int tid = threadIdx.x;

    for (int j = tid; j < 2048; j += 384) {
        int n = j & 63;
        int i4 = j >> 6;
        float4 val = make_float4(0.f, 0.f, 0.f, 0.f);
        if (n < nvalid)
            val = reinterpret_cast<const float4*>(x)[(size_t)(n0 + n) * 32 + i4];
        xs[(i4 * 4 + 0) * 64 + n] = val.x;
        xs[(i4 * 4 + 1) * 64 + n] = val.y;
        xs[(i4 * 4 + 2) * 64 + n] = val.z;
        xs[(i4 * 4 + 3) * 64 + n] = val.w;
    }
    __syncthreads();

    const int m  = tid >> 7;            // 0=Q, 1=K, 2=V (warp-uniform)
    const int tt = tid & 127;
    const int c4q = tt & 31;            // float4 col index (cols 4*c4q..+3)
    const int nb  = (tt >> 5) * 16;     // node base within tile

    const float* W    = (m == 0) ? Wq : (m == 1) ? Wk : Wv;
    const float* bias = (m == 0) ? bq : (m == 1) ? bk : bv;
    float* outp       = (m == 0) ? g_q : (m == 1) ? g_k : g_v;

    u64 acc[8][4];
#pragma unroll
    for (int np = 0; np < 8; np++)
#pragma unroll
        for (int c = 0; c < 4; c++) acc[np][c] = 0ull;

#pragma unroll 2
    for (int i = 0; i < 128; i++) {
        float4 w4 = reinterpret_cast<const float4*>(W)[i * 32 + c4q];
        u64 ww0 = pack2(w4.x, w4.x);
        u64 ww1 = pack2(w4.y, w4.y);
        u64 ww2 = pack2(w4.z, w4.z);
        u64 ww3 = pack2(w4.w, w4.w);
        const u64* xr = reinterpret_cast<const u64*>(&xs[i * 64 + nb]);
#pragma unroll
        for (int np = 0; np < 8; np++) {
            u64 xx = xr[np];
            ffma2(acc[np][0], xx, ww0);
            ffma2(acc[np][1], xx, ww1);
            ffma2(acc[np][2], xx, ww2);
            ffma2(acc[np][3], xx, ww3);
        }
    }

    float4 b4 = reinterpret_cast<const float4*>(bias)[c4q];
#pragma unroll
    for (int np = 0; np < 8; np++) {
        float2 p0 = unpack2(acc[np][0]);
        float2 p1 = unpack2(acc[np][1]);
        float2 p2 = unpack2(acc[np][2]);
        float2 p3 = unpack2(acc[np][3]);
        int node0 = n0 + nb + 2 * np;
        if (node0 < N_NODES) {
            float4 r0 = make_float4(p0.x + b4.x, p1.x + b4.y, p2.x + b4.z, p3.x + b4.w);
            reinterpret_cast<float4*>(outp)[(size_t)node0 * 32 + c4q] = r0;
        }
        if (node0 + 1 < N_NODES) {
            float4 r1 = make_float4(p0.y + b4.x, p1.y + b4.y, p2.y + b4.z, p3.y + b4.w);
            reinterpret_cast<float4*>(outp)[(size_t)(node0 + 1) * 32 + c4q] = r1;
        }
    }
}

// ---------------- degree count ----------------
__global__ void k_count(const int* __restrict__ ei)
{
    int e = blockIdx.x * blockDim.x + threadIdx.x;
    if (e < N_EDGES) {
        int t = ei[N_EDGES + e];
        atomicAdd(&g_deg[t], 1);
    }
}

// ---------------- 3-phase exclusive scan over g_deg -> g_off ----------------
__global__ void k_scanA()
{
    __shared__ int wsum[32];
    int b = blockIdx.x, tid = threadIdx.x;
    int i = b * 1024 + tid;
    int val = (i < N_NODES) ? g_deg[i] : 0;
    int lane = tid & 31, w = tid >> 5;
    for (int d = 16; d > 0; d >>= 1) val += __shfl_xor_sync(0xffffffffu, val, d);
    if (lane == 0) wsum[w] = val;
    __syncthreads();
    if (w == 0) {
        int s = wsum[lane];
        for (int d = 16; d > 0; d >>= 1) s += __shfl_xor_sync(0xffffffffu, s, d);
        if (lane == 0) g_bsum[b] = s;
    }
}

__global__ void k_scanB()
{
    if (threadIdx.x == 0) {
        int run = 0;
        for (int b = 0; b < SCAN_NB; b++) {
            int t = g_bsum[b];
            g_bsum[b] = run;
            run += t;
        }
    }
}

__global__ void k_scanC()
{
    __shared__ int wsum[32];
    int b = blockIdx.x, tid = threadIdx.x;
    int i = b * 1024 + tid;
    int val = (i < N_NODES) ? g_deg[i] : 0;
    int lane = tid & 31, w = tid >> 5;
    int incl = val;
    for (int d = 1; d < 32; d <<= 1) {
        int t = __shfl_up_sync(0xffffffffu, incl, d);
        if (lane >= d) incl += t;
    }
    if (lane == 31) wsum[w] = incl;
    __syncthreads();
    if (w == 0) {
        int s = wsum[lane];
        for (int d = 1; d < 32; d <<= 1) {
            int t = __shfl_up_sync(0xffffffffu, s, d);
            if (lane >= d) s += t;
        }
        wsum[lane] = s;
    }
    __syncthreads();
    int warp_off = (w == 0) ? 0 : wsum[w - 1];
    int excl = incl - val + warp_off + g_bsum[b];
    if (i < N_NODES) {
        g_off[i] = excl;
        if (i == N_NODES - 1) g_off[N_NODES] = excl + val;
    }
}

// ---------------- fill CSR: slot assignment + CSR-ordered source list ----------
__global__ void k_fill(const int* __restrict__ ei)
{
    int e = blockIdx.x * blockDim.x + threadIdx.x;
    if (e < N_EDGES) {
        int s = ei[e];
        int t = ei[N_EDGES + e];
        int pos = atomicAdd(&g_cursor[t], 1);
        g_src[pos] = s;
        g_epos[e] = pos;
    }
}

// ---------------- per-edge scores, written in CSR order ----------------
// Grid-stride warps; We register tile loaded ONCE per warp (was: per edge).
// lane = h*4 + j; lane owns dims 4*lane..4*lane+3.
__global__ void __launch_bounds__(256) k_scores(
    const int* __restrict__ ei, const float* __restrict__ ef,
    const float* __restrict__ We, const float* __restrict__ be)
{
    const int lane = threadIdx.x & 31;
    const int warp = (blockIdx.x * blockDim.x + threadIdx.x) >> 5;
    const int nwarps = (gridDim.x * blockDim.x) >> 5;
    const int h = lane >> 2, j = lane & 3;

    // per-lane slice of We: features [16j, 16j+16), head h
    float wreg[16];
#pragma unroll
    for (int ff = 0; ff < 16; ff++) wreg[ff] = We[(j * 16 + ff) * 8 + h];
    const float beh = be[h];

    for (int e = warp; e < N_EDGES; e += nwarps) {
        int s   = ei[e];
        int t   = ei[N_EDGES + e];
        int pos = g_epos[e];

        float4 q4 = reinterpret_cast<const float4*>(g_q)[(size_t)t * 32 + lane];
        float4 k4 = reinterpret_cast<const float4*>(g_k)[(size_t)s * 32 + lane];
        float dp = q4.x * k4.x + q4.y * k4.y + q4.z * k4.z + q4.w * k4.w;

        float bias = 0.f;
        const float4* ef4 = reinterpret_cast<const float4*>(ef) + (size_t)e * 16;
#pragma unroll
        for (int f4 = 0; f4 < 4; f4++) {
            float4 v = ef4[j * 4 + f4];
            bias += v.x * wreg[f4 * 4 + 0] + v.y * wreg[f4 * 4 + 1]
                  + v.z * wreg[f4 * 4 + 2] + v.w * wreg[f4 * 4 + 3];
        }

        dp   += __shfl_xor_sync(0xffffffffu, dp,   1);
        dp   += __shfl_xor_sync(0xffffffffu, dp,   2);
        bias += __shfl_xor_sync(0xffffffffu, bias, 1);
        bias += __shfl_xor_sync(0xffffffffu, bias, 2);

        if (j == 0) g_scores[(size_t)pos * 8 + h] = dp * 0.25f + bias + beh;
    }
}

// ---------------- segment softmax + weighted V aggregation (warp per node) ----
// scores + src are CSR-contiguous: only the v gather is irregular.
__global__ void __launch_bounds__(256) k_agg()
{
    int node = (blockIdx.x * blockDim.x + threadIdx.x) >> 5;
    if (node >= N_NODES) return;
    int lane = threadIdx.x & 31;
    int start = g_off[node], end = g_off[node + 1];

    const float* sc = g_scores + (size_t)start * 8;
    int cnt8 = (end - start) * 8;

    // pass 1: per-head max; lane L covers head L%8 on strided contiguous data
    float m = -INFINITY;
    for (int i = lane; i < cnt8; i += 32) m = fmaxf(m, sc[i]);
    m = fmaxf(m, __shfl_xor_sync(0xffffffffu, m, 8));
    m = fmaxf(m, __shfl_xor_sync(0xffffffffu, m, 16));
    float mh = __shfl_sync(0xffffffffu, m, lane >> 2);   // max for head lane>>2

    // pass 2: accumulate exp * v and denominator
    int h = lane >> 2;
    float4 acc = make_float4(0.f, 0.f, 0.f, 0.f);
    float den = 0.f;
    for (int idx = start; idx < end; idx++) {
        int s = g_src[idx];
        float p = __expf(sc[(idx - start) * 8 + h] - mh);
        float4 v4 = reinterpret_cast<const float4*>(g_v)[(size_t)s * 32 + lane];
        acc.x += p * v4.x; acc.y += p * v4.y;
        acc.z += p * v4.z; acc.w += p * v4.w;
        den += p;
    }
    float inv = 1.f / (den + 1e-10f);
    float4 r = make_float4(acc.x * inv, acc.y * inv, acc.z * inv, acc.w * inv);
    reinterpret_cast<float4*>(g_agg)[(size_t)node * 32 + lane] = r;
}

// ---------------- output GEMM: out = agg @ Wo + bo (f32x2 packed) ----------------
__global__ void __launch_bounds__(128) k_out(
    const float* __restrict__ Wo, const float* __restrict__ bo,
    float* __restrict__ out)
{
    __shared__ float xs[128 * 64];
    const int n0 = blockIdx.x * 64;
    const int nvalid = min(64, N_NODES - n0);
    const int tid = threadIdx.x;

    for (int j = tid; j < 2048; j += 128) {
        int n = j & 63;
        int i4 = j >> 6;
        float4 val = make_float4(0.f, 0.f, 0.f, 0.f);
        if (n < nvalid)
            val = reinterpret_cast<const float4*>(g_agg)[(size_t)(n0 + n) * 32 + i4];
        xs[(i4 * 4 + 0) * 64 + n] = val.x;
        xs[(i4 * 4 + 1) * 64 + n] = val.y;
        xs[(i4 * 4 + 2) * 64 + n] = val.z;
        xs[(i4 * 4 + 3) * 64 + n] = val.w;
    }
    __syncthreads();

    const int c4q = tid & 31;
    const int nb  = (tid >> 5) * 16;

    u64 acc[8][4];
#pragma unroll
    for (int np = 0; np < 8; np++)
#pragma unroll
        for (int c = 0; c < 4; c++) acc[np][c] = 0ull;

#pragma unroll 2
    for (int i = 0; i < 128; i++) {
        float4 w4 = reinterpret_cast<const float4*>(Wo)[i * 32 + c4q];
        u64 ww0 = pack2(w4.x, w4.x);
        u64 ww1 = pack2(w4.y, w4.y);
        u64 ww2 = pack2(w4.z, w4.z);
        u64 ww3 = pack2(w4.w, w4.w);
        const u64* xr = reinterpret_cast<const u64*>(&xs[i * 64 + nb]);
#pragma unroll
        for (int np = 0; np < 8; np++) {
            u64 xx = xr[np];
            ffma2(acc[np][0], xx, ww0);
            ffma2(acc[np][1], xx, ww1);
            ffma2(acc[np][2], xx, ww2);
            ffma2(acc[np][3], xx, ww3);
        }
    }

    float4 b4 = reinterpret_cast<const float4*>(bo)[c4q];
#pragma unroll
    for (int np = 0; np < 8; np++) {
        float2 p0 = unpack2(acc[np][0]);
        float2 p1 = unpack2(acc[np][1]);
        float2 p2 = unpack2(acc[np][2]);
        float2 p3 = unpack2(acc[np][3]);
        int node0 = n0 + nb + 2 * np;
        if (node0 < N_NODES) {
            float4 r0 = make_float4(p0.x + b4.x, p1.x + b4.y, p2.x + b4.z, p3.x + b4.w);
            reinterpret_cast<float4*>(out)[(size_t)node0 * 32 + c4q] = r0;
        }
        if (node0 + 1 < N_NODES) {
            float4 r1 = make_float4(p0.y + b4.x, p1.y + b4.y, p2.y + b4.z, p3.y + b4.w);
            reinterpret_cast<float4*>(out)[(size_t)(node0 + 1) * 32 + c4q] = r1;
        }
    }
}

// ---------------- launch ----------------
extern "C" void kernel_launch(void* const* d_in, const int* in_sizes, int n_in,
                              void* d_out, int out_size)
{
    const float* x  = (const float*)d_in[0];
    const int*   ei = (const int*)  d_in[1];
    const float* ef = (const float*)d_in[2];
    const float* Wq = (const float*)d_in[3];
    const float* bq = (const float*)d_in[4];
    const float* Wk = (const float*)d_in[5];
    const float* bk = (const float*)d_in[6];
    const float* Wv = (const float*)d_in[7];
    const float* bv = (const float*)d_in[8];
    const float* We = (const float*)d_in[9];
    const float* be = (const float*)d_in[10];
    const float* Wo = (const float*)d_in[11];
    const float* bo = (const float*)d_in[12];
    float* out = (float*)d_out;

    void* degPtr = nullptr; void* offPtr = nullptr; void* curPtr = nullptr;
    cudaGetSymbolAddress(&degPtr, g_deg);
    cudaGetSymbolAddress(&offPtr, g_off);
    cudaGetSymbolAddress(&curPtr, g_cursor);

    cudaMemsetAsync(degPtr, 0, N_NODES * sizeof(int), 0);

    k_qkv<<<(N_NODES + 63) / 64, 384>>>(x, Wq, bq, Wk, bk, Wv, bv);
    k_count<<<(N_EDGES + 255) / 256, 256>>>(ei);
    k_scanA<<<SCAN_NB, 1024>>>();
    k_scanB<<<1, 32>>>();
    k_scanC<<<SCAN_NB, 1024>>>();
    cudaMemcpyAsync(curPtr, offPtr, N_NODES * sizeof(int),
                    cudaMemcpyDeviceToDevice, 0);
    k_fill<<<(N_EDGES + 255) / 256, 256>>>(ei);
    k_scores<<<1184, 256>>>(ei, ef, We, be);   // 9472 warps, ~85 edges each
    k_agg<<<(N_NODES * 32 + 255) / 256, 256>>>();
    k_out<<<(N_NODES + 63) / 64, 128>>>(Wo, bo, out);
}